// round 1
// baseline (speedup 1.0000x reference)
#include <cuda_runtime.h>

// Problem constants
#define BATCH 32
#define CIN 8
#define COUT 8
#define DIN 16
#define DOUT 16
#define SSP 32
#define HW 1024            // 32*32
#define OC_TOTAL 1024      // CIN*COUT*DOUT
#define EPSV 1e-5f

// ---------------- scratch (device globals; no allocation allowed) ----------------
__device__ float g_votes [BATCH*OC_TOTAL*HW];          // 128 MB  [b][oc=(c*8+o)*16+d][u][v]
__device__ float g_pooled[BATCH*COUT*2*DOUT*HW];       // 64 MB   [b][o][i][d][u][v]
__device__ float g_rbuf  [BATCH*COUT*DOUT*HW];         // 16 MB   routing result (pre-gate)
__device__ float g_gate  [BATCH*COUT*DOUT*HW];         // 16 MB   conv3d output (pre-BN)
__device__ float g_bnacc [16];                         // per-o sum / sumsq
__device__ float g_bnAB  [16];                         // per-o affine A, B

// ---------------- packed f32x2 helpers (sm_100+) ----------------
typedef unsigned long long u64;
__device__ __forceinline__ u64 pk2(float lo, float hi){
    u64 r; asm("mov.b64 %0, {%1,%2};" : "=l"(r) : "f"(lo), "f"(hi)); return r;
}
__device__ __forceinline__ void upk2(u64 v, float& lo, float& hi){
    asm("mov.b64 {%0,%1}, %2;" : "=f"(lo), "=f"(hi) : "l"(v));
}
__device__ __forceinline__ u64 ffma2(u64 a, u64 b, u64 c){
    u64 d; asm("fma.rn.f32x2 %0, %1, %2, %3;" : "=l"(d) : "l"(a), "l"(b), "l"(c)); return d;
}

// ---------------- K0: zero BN accumulators ----------------
__global__ void k0_zero(){
    if (threadIdx.x < 16) g_bnacc[threadIdx.x] = 0.f;
}

// ---------------- K1: conv2d (caps * Wt + bt -> votes) ----------------
// Block: (b, group of 16 consecutive oc). 256 threads.
// Thread -> row u = tid>>3, base col w = tid&7, positions v = w + 8j (j=0..3).
// Accumulators pair over oc (oc,oc+1) as f32x2; input broadcast-packed (x,x).
#define K1_ROWSTRIDE 40                       // bank-conflict-free: (40u+w)%32 splits by octet
#define K1_SIN (DIN*34*K1_ROWSTRIDE)          // 21760 floats
#define K1_SW  (144*16)                       // [tap][oc_local]
#define K1_SMEM ((K1_SIN + K1_SW + 16)*4)     // 96320 B

__global__ __launch_bounds__(256,2) void k1_conv2d(
        const float* __restrict__ caps, const float* __restrict__ Wt,
        const float* __restrict__ bt){
    extern __shared__ __align__(16) float sm1[];
    float* sIn = sm1;
    float* sW  = sm1 + K1_SIN;
    float* sB  = sW + K1_SW;

    int b = blockIdx.y;
    int ocbase = blockIdx.x * 16;
    int tid = threadIdx.x;

    // stage padded input tile [din][34][34] (row stride 40)
    const float* cb = caps + (size_t)b*(DIN*HW);
    for (int i = tid; i < DIN*34*34; i += 256){
        int din = i / (34*34);
        int rem = i - din*(34*34);
        int py = rem / 34, px = rem - py*34;
        int y = py-1, x = px-1;
        float v = 0.f;
        if ((unsigned)y < 32u && (unsigned)x < 32u) v = cb[din*HW + y*32 + x];
        sIn[din*(34*K1_ROWSTRIDE) + py*K1_ROWSTRIDE + px] = v;
    }
    // stage weights transposed to [tap][oc_local] (coalesced global read)
    for (int i = tid; i < 16*144; i += 256){
        int oc = i / 144, tap = i - oc*144;
        sW[tap*16 + oc] = Wt[(size_t)(ocbase)*144 + i];
    }
    if (tid < 16) sB[tid] = bt[ocbase + tid];
    __syncthreads();

    int u = tid >> 3;
    int w = tid & 7;

    u64 acc[4][8];
    #pragma unroll
    for (int p = 0; p < 8; p++){
        u64 bias = pk2(sB[2*p], sB[2*p+1]);
        acc[0][p]=bias; acc[1][p]=bias; acc[2][p]=bias; acc[3][p]=bias;
    }

    for (int din = 0; din < DIN; din++){
        const float* rb = sIn + din*(34*K1_ROWSTRIDE);
        #pragma unroll
        for (int ky = 0; ky < 3; ky++){
            const float* r = rb + (u+ky)*K1_ROWSTRIDE + w;
            float xs[4][3];
            #pragma unroll
            for (int j = 0; j < 4; j++){
                xs[j][0] = r[8*j+0]; xs[j][1] = r[8*j+1]; xs[j][2] = r[8*j+2];
            }
            #pragma unroll
            for (int kx = 0; kx < 3; kx++){
                u64 xd0 = pk2(xs[0][kx], xs[0][kx]);
                u64 xd1 = pk2(xs[1][kx], xs[1][kx]);
                u64 xd2 = pk2(xs[2][kx], xs[2][kx]);
                u64 xd3 = pk2(xs[3][kx], xs[3][kx]);
                const u64* wp = (const u64*)(sW + (din*9 + ky*3 + kx)*16);
                #pragma unroll
                for (int p = 0; p < 8; p++){
                    u64 wv = wp[p];
                    acc[0][p] = ffma2(xd0, wv, acc[0][p]);
                    acc[1][p] = ffma2(xd1, wv, acc[1][p]);
                    acc[2][p] = ffma2(xd2, wv, acc[2][p]);
                    acc[3][p] = ffma2(xd3, wv, acc[3][p]);
                }
            }
        }
    }

    // store votes: coalesced (8 consecutive v per octet of lanes)
    float* vb = g_votes + (size_t)b*(OC_TOTAL*HW) + (size_t)ocbase*HW + u*32 + w;
    #pragma unroll
    for (int p = 0; p < 8; p++){
        #pragma unroll
        for (int j = 0; j < 4; j++){
            float lo, hi; upk2(acc[j][p], lo, hi);
            vb[(2*p  )*HW + 8*j] = lo;
            vb[(2*p+1)*HW + 8*j] = hi;
        }
    }
}

// ---------------- K2: values + pooled(max/mean) + routing result r ----------------
// Block fixed (b, o); 64 blocks of 256 threads cover the 16384 positions.
__global__ __launch_bounds__(256) void k2_values(
        const float* __restrict__ Wv, const float* __restrict__ bv){
    __shared__ __align__(16) float sWv[256];   // [c][m] transposed
    __shared__ float sBv[32];
    int b = blockIdx.z, o = blockIdx.y;
    int tid = threadIdx.x;
    int pos = blockIdx.x*256 + tid;            // = d*1024 + u*32 + v

    { int m = tid >> 3, c = tid & 7; sWv[c*32 + m] = Wv[o*256 + tid]; }
    if (tid < 32) sBv[tid] = bv[o*32 + tid];
    __syncthreads();

    int d = pos >> 10, uv = pos & 1023;
    const float* vp = g_votes + (size_t)b*(OC_TOTAL*HW) + (size_t)(o*16 + d)*HW + uv;
    float vc[8];
    #pragma unroll
    for (int c = 0; c < 8; c++) vc[c] = vp[(size_t)c*128*HW];

    u64 acc[16];
    #pragma unroll
    for (int mp = 0; mp < 16; mp++) acc[mp] = pk2(sBv[2*mp], sBv[2*mp+1]);
    #pragma unroll
    for (int c = 0; c < 8; c++){
        u64 x = pk2(vc[c], vc[c]);
        const u64* wp = (const u64*)(sWv + c*32);
        #pragma unroll
        for (int mp = 0; mp < 16; mp++) acc[mp] = ffma2(wp[mp], x, acc[mp]);
    }
    float val[32];
    #pragma unroll
    for (int mp = 0; mp < 16; mp++) upk2(acc[mp], val[2*mp], val[2*mp+1]);

    // pooled: max & mean over m
    float mx = val[0], sm = val[0];
    #pragma unroll
    for (int m = 1; m < 32; m++){ mx = fmaxf(mx, val[m]); sm += val[m]; }
    size_t pbase = (size_t)((b*8 + o)*2)*(DOUT*HW) + pos;
    g_pooled[pbase]           = mx;
    g_pooled[pbase + DOUT*HW] = sm * (1.f/32.f);

    // routing (gate-independent): m = k*8 + c
    float rnum = 0.f, rden = 0.f;
    #pragma unroll
    for (int c = 0; c < 8; c++){
        float a0 = val[c], a1 = val[c+8], a2 = val[c+16], a3 = val[c+24];
        float s1 = a0+a1+a2+a3;
        float s2 = a0*a0 + a1*a1 + a2*a2 + a3*a3;
        float mu  = s1 * 0.25f;
        float var = s2 * 0.25f - mu*mu;
        float sd  = sqrtf(fmaxf(var, 0.f));
        float wgt = 1.f / sd;                  // exp(-log sd)
        rden += wgt; rnum += wgt * mu;
    }
    g_rbuf[(size_t)(b*8 + o)*(DOUT*HW) + pos] = rnum / rden;
}

// ---------------- K3: conv3d gate + BN partial sums ----------------
// Block: (u-tile of 8, o, b); smem tile [2][18][10][34]; thread=(u_local,v), all d.
#define K3_T (2*18*10*34)   // 12240 floats = 48960 B
__global__ __launch_bounds__(256) void k3_conv3d(const float* __restrict__ Ws){
    extern __shared__ float sT[];
    __shared__ float sWs[54];
    __shared__ float sred[16];
    int ut = blockIdx.x, o = blockIdx.y, b = blockIdx.z;
    int tid = threadIdx.x;
    if (tid < 54) sWs[tid] = Ws[tid];
    const float* pb = g_pooled + (size_t)(b*8 + o)*2*(DOUT*HW);
    int u0 = ut*8;
    for (int idx = tid; idx < K3_T; idx += 256){
        int vx = idx % 34; int r1 = idx / 34;
        int uy = r1 % 10;  int r2 = r1 / 10;
        int dz = r2 % 18;  int i  = r2 / 18;
        int d = dz - 1, u = u0 + uy - 1, v = vx - 1;
        float x = 0.f;
        if ((unsigned)d < 16u && (unsigned)u < 32u && (unsigned)v < 32u)
            x = pb[i*(DOUT*HW) + d*HW + u*32 + v];
        sT[idx] = x;
    }
    __syncthreads();

    int ul = tid >> 5, v = tid & 31;
    float acc[16];
    #pragma unroll
    for (int dI = 0; dI < 16; dI++) acc[dI] = 0.f;

    #pragma unroll
    for (int dd = 0; dd < 18; dd++){
        float t[18];
        #pragma unroll
        for (int i = 0; i < 2; i++)
            #pragma unroll
            for (int dy = 0; dy < 3; dy++)
                #pragma unroll
                for (int dx = 0; dx < 3; dx++)
                    t[i*9 + dy*3 + dx] = sT[((i*18 + dd)*10 + ul + dy)*34 + v + dx];
        #pragma unroll
        for (int dz = 0; dz < 3; dz++){
            int dO = dd - dz;                 // output d receiving plane dd-1 with weight index dz
            if (dO >= 0 && dO < 16){
                float a = acc[dO];
                #pragma unroll
                for (int i = 0; i < 2; i++)
                    #pragma unroll
                    for (int dy = 0; dy < 3; dy++)
                        #pragma unroll
                        for (int dx = 0; dx < 3; dx++)
                            a += t[i*9 + dy*3 + dx] * sWs[(i*3 + dz)*9 + dy*3 + dx];
                acc[dO] = a;
            }
        }
    }

    float s = 0.f, q = 0.f;
    float* gb = g_gate + (size_t)(b*8 + o)*(DOUT*HW) + (u0 + ul)*32 + v;
    #pragma unroll
    for (int dI = 0; dI < 16; dI++){
        gb[dI*HW] = acc[dI];
        s += acc[dI]; q += acc[dI]*acc[dI];
    }
    #pragma unroll
    for (int off = 16; off; off >>= 1){
        s += __shfl_xor_sync(0xffffffffu, s, off);
        q += __shfl_xor_sync(0xffffffffu, q, off);
    }
    if ((tid & 31) == 0){ sred[tid>>5] = s; sred[8 + (tid>>5)] = q; }
    __syncthreads();
    if (tid == 0){
        float S = 0.f, Q = 0.f;
        for (int i = 0; i < 8; i++){ S += sred[i]; Q += sred[8+i]; }
        atomicAdd(&g_bnacc[o],     S);
        atomicAdd(&g_bnacc[8 + o], Q);
    }
}

// ---------------- K4: finalize BN affine ----------------
__global__ void k4_bn(const float* __restrict__ bng, const float* __restrict__ bnb){
    int o = threadIdx.x;
    if (o < 8){
        const float n = (float)(BATCH*DOUT*HW);       // 524288
        float mu  = g_bnacc[o] / n;
        float var = g_bnacc[8+o] / n - mu*mu;
        float A = bng[0] / sqrtf(var + EPSV);
        g_bnAB[o]     = A;
        g_bnAB[8 + o] = bnb[0] - mu*A;
    }
}

// ---------------- K5: gate*routing + LayerNorm + transposed write ----------------
// One block per (b,o): 16384 elems staged in smem, single-pass stats.
__global__ __launch_bounds__(256) void k5_final(
        const float* __restrict__ lng, const float* __restrict__ lnb,
        float* __restrict__ out){
    extern __shared__ float scn[];   // 16384 floats
    __shared__ float sred[16];
    __shared__ float sMV[2];
    int b = blockIdx.x, o = blockIdx.y;
    int tid = threadIdx.x;
    float A = g_bnAB[o], Bb = g_bnAB[8 + o];
    const float* gg = g_gate + (size_t)(b*8 + o)*16384;
    const float* rr = g_rbuf + (size_t)(b*8 + o)*16384;
    float s = 0.f, q = 0.f;
    #pragma unroll 8
    for (int j = 0; j < 64; j++){
        int p = tid + j*256;
        float gn = gg[p]*A + Bb;
        float sc = 1.f + 1.f/(1.f + expf(-gn));
        float cn = rr[p] * sc;
        scn[p] = cn; s += cn; q += cn*cn;
    }
    #pragma unroll
    for (int off = 16; off; off >>= 1){
        s += __shfl_xor_sync(0xffffffffu, s, off);
        q += __shfl_xor_sync(0xffffffffu, q, off);
    }
    if ((tid & 31) == 0){ sred[tid>>5] = s; sred[8 + (tid>>5)] = q; }
    __syncthreads();
    if (tid == 0){
        float S = 0.f, Q = 0.f;
        for (int i = 0; i < 8; i++){ S += sred[i]; Q += sred[8+i]; }
        float mean = S * (1.f/16384.f);
        float var  = Q * (1.f/16384.f) - mean*mean;
        sMV[0] = mean;
        sMV[1] = 1.f / sqrtf(var + EPSV);
    }
    __syncthreads();
    float mean = sMV[0], inv = sMV[1];
    float* ob = out + ((size_t)o*BATCH + b)*16384;
    #pragma unroll 8
    for (int j = 0; j < 64; j++){
        int p = tid + j*256;
        ob[p] = (scn[p] - mean)*inv*lng[p] + lnb[p];
    }
}

// ---------------- launch ----------------
extern "C" void kernel_launch(void* const* d_in, const int* in_sizes, int n_in,
                              void* d_out, int out_size){
    // Map inputs by element count (robust to ordering); ties keep dict order.
    const float *caps=0,*Wt=0,*bt=0,*Wv=0,*bv=0,*Ws=0,*bng=0,*bnb=0,*lng=0,*lnb=0;
    int seen1 = 0, seen16k = 0;
    for (int i = 0; i < n_in; i++){
        const float* p = (const float*)d_in[i];
        switch (in_sizes[i]){
            case 524288: caps = p; break;
            case 147456: Wt = p; break;
            case 1024:   bt = p; break;
            case 2048:   Wv = p; break;
            case 256:    bv = p; break;
            case 54:     Ws = p; break;
            case 1:      if (!seen1){ bng = p; seen1 = 1; } else bnb = p; break;
            case 16384:  if (!seen16k){ lng = p; seen16k = 1; } else lnb = p; break;
            default: break;
        }
    }
    float* out = (float*)d_out;

    cudaFuncSetAttribute(k1_conv2d, cudaFuncAttributeMaxDynamicSharedMemorySize, K1_SMEM);
    cudaFuncSetAttribute(k3_conv3d, cudaFuncAttributeMaxDynamicSharedMemorySize, K3_T*4);
    cudaFuncSetAttribute(k5_final,  cudaFuncAttributeMaxDynamicSharedMemorySize, 16384*4);

    k0_zero<<<1, 32>>>();
    k1_conv2d<<<dim3(64, 32), 256, K1_SMEM>>>(caps, Wt, bt);
    k2_values<<<dim3(64, 8, 32), 256>>>(Wv, bv);
    k3_conv3d<<<dim3(4, 8, 32), 256, K3_T*4>>>(Ws);
    k4_bn<<<1, 32>>>(bng, bnb);
    k5_final<<<dim3(32, 8), 256, 16384*4>>>(lng, lnb, out);
}